// round 3
// baseline (speedup 1.0000x reference)
#include <cuda_runtime.h>
#include <cuda_bf16.h>
#include <cstdint>

// ---------------- problem constants ----------------
#define SEQ   512
#define BATCH 64
#define EMB   512
#define HID   1024
#define G4    4096           // 4*HID
#define NCTA  128            // persistent CTAs for recurrence
#define HPC   8              // hidden units per CTA
#define CPC   32             // gate columns per CTA (4 gates * HPC)

// ---------------- device scratch (static: no allocations allowed) ----------------
__device__ float    d_Wfold[EMB * G4];                       // 8 MB
__device__ float    d_bias2[G4];
__device__ float    d_gates[(size_t)SEQ * NCTA * BATCH * CPC]; // 512 MB, layout [t][cta][b][32]
__device__ float    d_hbuf[2][BATCH * HID];                  // double-buffered h
__device__ unsigned d_ctr;                                   // step completion counter

// ---------------- helpers ----------------
__device__ __forceinline__ float tf32r(float x) {
    uint32_t u;
    asm("cvt.rna.tf32.f32 %0, %1;" : "=r"(u) : "f"(x));
    return __uint_as_float(u);
}

__device__ __forceinline__ void mma_tf32(float c[4],
                                         uint32_t a0, uint32_t a1, uint32_t a2, uint32_t a3,
                                         uint32_t b0, uint32_t b1) {
    asm volatile(
        "mma.sync.aligned.m16n8k8.row.col.f32.tf32.tf32.f32 "
        "{%0,%1,%2,%3}, {%4,%5,%6,%7}, {%8,%9}, {%0,%1,%2,%3};\n"
        : "+f"(c[0]), "+f"(c[1]), "+f"(c[2]), "+f"(c[3])
        : "r"(a0), "r"(a1), "r"(a2), "r"(a3), "r"(b0), "r"(b1));
}

__device__ __forceinline__ float sigf(float x) {
    return __fdividef(1.f, 1.f + __expf(-x));
}
__device__ __forceinline__ float tanf_(float x) {
    return __fdividef(2.f, 1.f + __expf(-2.f * x)) - 1.f;
}

// ================= K1: fold  Wfold = bridge_w @ w_ih  (512x4096, K=512, fp32 SIMT) =================
__global__ __launch_bounds__(256) void k_fold(const float* __restrict__ bw,
                                              const float* __restrict__ wih) {
    __shared__ float As[64][17];
    __shared__ float Bs[16][68];
    const int tid = threadIdx.x;
    const int n0 = blockIdx.x * 64, m0 = blockIdx.y * 64;
    const int tx = tid & 15, ty = tid >> 4;
    const int ar = tid >> 2, ac4 = (tid & 3) * 4;
    const int br = tid >> 4, bc4 = (tid & 15) * 4;

    float acc[4][4] = {};
    for (int kc = 0; kc < 512; kc += 16) {
        float4 av = *(const float4*)(bw + (size_t)(m0 + ar) * 512 + kc + ac4);
        As[ar][ac4 + 0] = av.x; As[ar][ac4 + 1] = av.y;
        As[ar][ac4 + 2] = av.z; As[ar][ac4 + 3] = av.w;
        float4 bv = *(const float4*)(wih + (size_t)(kc + br) * G4 + n0 + bc4);
        Bs[br][bc4 + 0] = bv.x; Bs[br][bc4 + 1] = bv.y;
        Bs[br][bc4 + 2] = bv.z; Bs[br][bc4 + 3] = bv.w;
        __syncthreads();
#pragma unroll
        for (int k = 0; k < 16; k++) {
            float a[4], b[4];
#pragma unroll
            for (int i = 0; i < 4; i++) a[i] = As[ty * 4 + i][k];
#pragma unroll
            for (int j = 0; j < 4; j++) b[j] = Bs[k][tx * 4 + j];
#pragma unroll
            for (int i = 0; i < 4; i++)
#pragma unroll
                for (int j = 0; j < 4; j++) acc[i][j] += a[i] * b[j];
        }
        __syncthreads();
    }
#pragma unroll
    for (int i = 0; i < 4; i++)
#pragma unroll
        for (int j = 0; j < 4; j++)
            d_Wfold[(size_t)(m0 + ty * 4 + i) * G4 + n0 + tx * 4 + j] = acc[i][j];
}

// ================= Kb: bias2 = bridge_b @ w_ih + b_ih + b_hh ; also reset counter ================
__global__ __launch_bounds__(256) void k_bias(const float* __restrict__ bb,
                                              const float* __restrict__ wih,
                                              const float* __restrict__ bih,
                                              const float* __restrict__ bhh) {
    const int g = blockIdx.x * blockDim.x + threadIdx.x;
    if (g == 0) d_ctr = 0u;
    if (g >= G4) return;
    float acc = bih[g] + bhh[g];
    for (int e = 0; e < 512; e++) acc += bb[e] * wih[(size_t)e * G4 + g];
    d_bias2[g] = acc;
}

// ================= K2: gates = gather(emb) @ Wfold + bias2  (tf32 mma) ================
// grid = (G4/64, SEQ); block tile M=64(batch of one timestep) x N=64, K=512
__global__ __launch_bounds__(256) void k_gates(const int* __restrict__ x,
                                               const float* __restrict__ emb) {
    __shared__ float As[64 * 20];   // [64][20] tf32-rounded
    __shared__ float Bs[16 * 68];   // [16][68]
    const int tid  = threadIdx.x;
    const int t    = blockIdx.y;
    const int n0   = blockIdx.x * 64;
    const int lane = tid & 31, wid = tid >> 5;
    const int gid  = lane >> 2, t4 = lane & 3;
    const int wm   = wid >> 2, wn = wid & 3;   // 2x4 warp grid, warp tile 32x16

    const int ar = tid >> 2, ac4 = (tid & 3) * 4;
    const int br = tid >> 4, bc4 = (tid & 15) * 4;
    const int tok = x[(size_t)ar * SEQ + t];
    const float* arow  = emb + (size_t)tok * EMB;
    const float* bbase = d_Wfold + (size_t)br * G4 + n0 + bc4;

    float C[2][2][4] = {};

    for (int k0 = 0; k0 < 512; k0 += 16) {
        float4 av = *(const float4*)(arow + k0 + ac4);
        As[ar * 20 + ac4 + 0] = tf32r(av.x); As[ar * 20 + ac4 + 1] = tf32r(av.y);
        As[ar * 20 + ac4 + 2] = tf32r(av.z); As[ar * 20 + ac4 + 3] = tf32r(av.w);
        float4 bv = *(const float4*)(bbase + (size_t)k0 * G4);
        Bs[br * 68 + bc4 + 0] = tf32r(bv.x); Bs[br * 68 + bc4 + 1] = tf32r(bv.y);
        Bs[br * 68 + bc4 + 2] = tf32r(bv.z); Bs[br * 68 + bc4 + 3] = tf32r(bv.w);
        __syncthreads();
#pragma unroll
        for (int ks = 0; ks < 16; ks += 8) {
            uint32_t a[2][4], b[2][2];
#pragma unroll
            for (int mt = 0; mt < 2; mt++) {
                const int r = wm * 32 + mt * 16 + gid;
                a[mt][0] = __float_as_uint(As[r * 20 + ks + t4]);
                a[mt][1] = __float_as_uint(As[(r + 8) * 20 + ks + t4]);
                a[mt][2] = __float_as_uint(As[r * 20 + ks + 4 + t4]);
                a[mt][3] = __float_as_uint(As[(r + 8) * 20 + ks + 4 + t4]);
            }
#pragma unroll
            for (int nt = 0; nt < 2; nt++) {
                const int c = wn * 16 + nt * 8 + gid;
                b[nt][0] = __float_as_uint(Bs[(ks + t4) * 68 + c]);
                b[nt][1] = __float_as_uint(Bs[(ks + 4 + t4) * 68 + c]);
            }
#pragma unroll
            for (int mt = 0; mt < 2; mt++)
#pragma unroll
                for (int nt = 0; nt < 2; nt++)
                    mma_tf32(C[mt][nt], a[mt][0], a[mt][1], a[mt][2], a[mt][3],
                             b[nt][0], b[nt][1]);
        }
        __syncthreads();
    }

    // epilogue: +bias2, permute into [t][cta][b][32] (col l = gate*8 + hid)
#pragma unroll
    for (int mt = 0; mt < 2; mt++) {
#pragma unroll
        for (int nt = 0; nt < 2; nt++) {
            const int r0 = wm * 32 + mt * 16 + gid;
            const int c0 = n0 + wn * 16 + nt * 8 + t4 * 2;
#pragma unroll
            for (int e = 0; e < 4; e++) {
                const int b = r0 + ((e >> 1) ? 8 : 0);
                const int n = c0 + (e & 1);
                const float v = C[mt][nt][e] + d_bias2[n];
                const int cta   = (n & 1023) >> 3;
                const int local = ((n >> 10) << 3) + (n & 7);
                d_gates[(((size_t)t * NCTA + cta) * BATCH + b) * CPC + local] = v;
            }
        }
    }
}

// ================= K3: persistent LSTM recurrence ================
// 128 CTAs, CTA j owns hidden units [j*8, j*8+8), gate cols ordered [i f g o]x8 in SMEM.
// SMEM: Ws[1024][36] tf32 (144KB) + hs[64][68] (17KB) + gs[64][33] (8.25KB) + cs[512] (2KB)
#define K3_SMEM ((1024 * 36 + 64 * 68 + 64 * 33 + 512) * 4)

__global__ __launch_bounds__(256, 1) void k_lstm(const float* __restrict__ whh) {
    extern __shared__ float sm[];
    float* Ws = sm;                      // [1024][36]
    float* hs = sm + 1024 * 36;          // [64][68]
    float* gs = hs + 64 * 68;            // [64][33]
    float* cs = gs + 64 * 33;            // [512]

    const int tid  = threadIdx.x;
    const int j    = blockIdx.x;
    const int lane = tid & 31, wid = tid >> 5;
    const int gid  = lane >> 2, t4 = lane & 3;
    const int wm   = wid >> 1, wn = wid & 1;   // 4x2 warp grid, warp tile 16x16

    // load w_hh slice (tf32-rounded)
    for (int idx = tid; idx < 1024 * CPC; idx += 256) {
        const int k = idx >> 5, l = idx & 31;
        const int gcol = ((l >> 3) << 10) + j * HPC + (l & 7);
        Ws[k * 36 + l] = tf32r(whh[(size_t)k * G4 + gcol]);
    }
    for (int q = tid; q < 512; q += 256) cs[q] = 0.f;
    __syncthreads();

    for (int t = 0; t < SEQ; t++) {
        if (t > 0) {
            if (tid == 0) {
                volatile unsigned* p = &d_ctr;
                const unsigned tgt = (unsigned)t * NCTA;
                while (*p < tgt) {}
            }
            __syncthreads();
            const float* hprev = d_hbuf[(t - 1) & 1];

            float Cf[2][4] = {};
            for (int kc = 0; kc < 16; kc++) {         // K chunks of 64
#pragma unroll
                for (int i = 0; i < 4; i++) {         // fill hs[64][64] (tf32)
                    const int f4 = tid + i * 256;
                    const int r = f4 >> 4, c4 = (f4 & 15) * 4;
                    float4 v = __ldcg((const float4*)(hprev + (size_t)r * HID + kc * 64 + c4));
                    v.x = tf32r(v.x); v.y = tf32r(v.y); v.z = tf32r(v.z); v.w = tf32r(v.w);
                    *(float4*)(hs + r * 68 + c4) = v;
                }
                __syncthreads();
#pragma unroll
                for (int ks = 0; ks < 64; ks += 8) {
                    const int arow = wm * 16 + gid;
                    const uint32_t a0 = __float_as_uint(hs[arow * 68 + ks + t4]);
                    const uint32_t a1 = __float_as_uint(hs[(arow + 8) * 68 + ks + t4]);
                    const uint32_t a2 = __float_as_uint(hs[arow * 68 + ks + 4 + t4]);
                    const uint32_t a3 = __float_as_uint(hs[(arow + 8) * 68 + ks + 4 + t4]);
                    const int kg = kc * 64 + ks;
#pragma unroll
                    for (int nt = 0; nt < 2; nt++) {
                        const int c = wn * 16 + nt * 8 + gid;
                        const uint32_t b0 = __float_as_uint(Ws[(kg + t4) * 36 + c]);
                        const uint32_t b1 = __float_as_uint(Ws[(kg + 4 + t4) * 36 + c]);
                        mma_tf32(Cf[nt], a0, a1, a2, a3, b0, b1);
                    }
                }
                __syncthreads();
            }
            // scatter C fragments to gs
            {
                const int r0 = wm * 16 + gid;
#pragma unroll
                for (int nt = 0; nt < 2; nt++) {
                    const int c = wn * 16 + nt * 8 + t4 * 2;
                    gs[r0 * 33 + c]           = Cf[nt][0];
                    gs[r0 * 33 + c + 1]       = Cf[nt][1];
                    gs[(r0 + 8) * 33 + c]     = Cf[nt][2];
                    gs[(r0 + 8) * 33 + c + 1] = Cf[nt][3];
                }
            }
            __syncthreads();
        }

        // fused LSTM cell epilogue: 512 (b,hid) pairs, 2 per thread
#pragma unroll
        for (int i = 0; i < 2; i++) {
            const int q = tid + i * 256;
            const int b = q >> 3, hid = q & 7;
            const float* gx = d_gates + (((size_t)t * NCTA + j) * BATCH + b) * CPC;
            float g0 = gx[hid], g1 = gx[8 + hid], g2 = gx[16 + hid], g3 = gx[24 + hid];
            if (t > 0) {
                g0 += gs[b * 33 + hid];
                g1 += gs[b * 33 + 8 + hid];
                g2 += gs[b * 33 + 16 + hid];
                g3 += gs[b * 33 + 24 + hid];
            }
            const float ig = sigf(g0), fg = sigf(g1), gg = tanf_(g2), og = sigf(g3);
            const float c = fg * cs[q] + ig * gg;
            cs[q] = c;
            d_hbuf[t & 1][(size_t)b * HID + j * HPC + hid] = og * tanf_(c);
        }
        __threadfence();
        __syncthreads();
        if (tid == 0) atomicAdd(&d_ctr, 1u);
    }
}

// ================= K4: logits = h_last @ out_w + out_b ================
__global__ void k_out(const float* __restrict__ ow, const float* __restrict__ ob,
                      float* __restrict__ out) {
    const int tid = threadIdx.x;
    if (tid >= 128) return;
    const int b = tid >> 1, n = tid & 1;
    const float* h = d_hbuf[1] + (size_t)b * HID;   // step 511 wrote buffer 1
    float acc = ob[n];
    for (int k = 0; k < HID; k++) acc += h[k] * ow[k * 2 + n];
    out[b * 2 + n] = acc;
}

// ================= launch ================
extern "C" void kernel_launch(void* const* d_in, const int* in_sizes, int n_in,
                              void* d_out, int out_size) {
    const int*   x      = (const int*)  d_in[0];
    const float* embT   = (const float*)d_in[1];
    const float* bw     = (const float*)d_in[2];
    const float* bb     = (const float*)d_in[3];
    const float* wih    = (const float*)d_in[4];
    const float* whh    = (const float*)d_in[5];
    const float* bih    = (const float*)d_in[6];
    const float* bhh    = (const float*)d_in[7];
    const float* ow     = (const float*)d_in[8];
    const float* ob     = (const float*)d_in[9];
    float*       out    = (float*)d_out;

    cudaFuncSetAttribute(k_lstm, cudaFuncAttributeMaxDynamicSharedMemorySize, K3_SMEM);

    k_fold<<<dim3(G4 / 64, EMB / 64), 256>>>(bw, wih);
    k_bias<<<dim3(G4 / 256), 256>>>(bb, wih, bih, bhh);
    k_gates<<<dim3(G4 / 64, SEQ), 256>>>(x, embT);
    k_lstm<<<NCTA, 256, K3_SMEM>>>(whh);
    k_out<<<1, 128>>>(ow, ob, out);
}

// round 4
// speedup vs baseline: 1.0005x; 1.0005x over previous
#include <cuda_runtime.h>
#include <cuda_bf16.h>
#include <cstdint>

// ---------------- problem constants ----------------
#define SEQ   512
#define BATCH 64
#define EMB   512
#define HID   1024
#define G4    4096           // 4*HID
#define NCTA  128            // persistent CTAs for recurrence
#define HPC   8              // hidden units per CTA
#define CPC   32             // gate columns per CTA (4 gates * HPC)

// ---------------- device scratch (static: no allocations allowed) ----------------
__device__ float    d_Wfold[EMB * G4];                       // 8 MB
__device__ float    d_bias2[G4];
__device__ float    d_gates[(size_t)SEQ * NCTA * BATCH * CPC]; // 512 MB, layout [t][cta][b][32]
__device__ float    d_hbuf[2][BATCH * HID];                  // double-buffered h
__device__ unsigned d_ctr;                                   // step completion counter

// ---------------- helpers ----------------
__device__ __forceinline__ float tf32r(float x) {
    uint32_t u;
    asm("cvt.rna.tf32.f32 %0, %1;" : "=r"(u) : "f"(x));
    return __uint_as_float(u);
}

__device__ __forceinline__ void mma_tf32(float c[4],
                                         uint32_t a0, uint32_t a1, uint32_t a2, uint32_t a3,
                                         uint32_t b0, uint32_t b1) {
    asm volatile(
        "mma.sync.aligned.m16n8k8.row.col.f32.tf32.tf32.f32 "
        "{%0,%1,%2,%3}, {%4,%5,%6,%7}, {%8,%9}, {%0,%1,%2,%3};\n"
        : "+f"(c[0]), "+f"(c[1]), "+f"(c[2]), "+f"(c[3])
        : "r"(a0), "r"(a1), "r"(a2), "r"(a3), "r"(b0), "r"(b1));
}

__device__ __forceinline__ float sigf(float x) {
    return __fdividef(1.f, 1.f + __expf(-x));
}
__device__ __forceinline__ float tanf_(float x) {
    return __fdividef(2.f, 1.f + __expf(-2.f * x)) - 1.f;
}

// ================= K1: fold  Wfold = bridge_w @ w_ih  (512x4096, K=512, fp32 SIMT) =================
__global__ __launch_bounds__(256) void k_fold(const float* __restrict__ bw,
                                              const float* __restrict__ wih) {
    __shared__ float As[64][17];
    __shared__ float Bs[16][68];
    const int tid = threadIdx.x;
    const int n0 = blockIdx.x * 64, m0 = blockIdx.y * 64;
    const int tx = tid & 15, ty = tid >> 4;
    const int ar = tid >> 2, ac4 = (tid & 3) * 4;
    const int br = tid >> 4, bc4 = (tid & 15) * 4;

    float acc[4][4] = {};
    for (int kc = 0; kc < 512; kc += 16) {
        float4 av = *(const float4*)(bw + (size_t)(m0 + ar) * 512 + kc + ac4);
        As[ar][ac4 + 0] = av.x; As[ar][ac4 + 1] = av.y;
        As[ar][ac4 + 2] = av.z; As[ar][ac4 + 3] = av.w;
        float4 bv = *(const float4*)(wih + (size_t)(kc + br) * G4 + n0 + bc4);
        Bs[br][bc4 + 0] = bv.x; Bs[br][bc4 + 1] = bv.y;
        Bs[br][bc4 + 2] = bv.z; Bs[br][bc4 + 3] = bv.w;
        __syncthreads();
#pragma unroll
        for (int k = 0; k < 16; k++) {
            float a[4], b[4];
#pragma unroll
            for (int i = 0; i < 4; i++) a[i] = As[ty * 4 + i][k];
#pragma unroll
            for (int j = 0; j < 4; j++) b[j] = Bs[k][tx * 4 + j];
#pragma unroll
            for (int i = 0; i < 4; i++)
#pragma unroll
                for (int j = 0; j < 4; j++) acc[i][j] += a[i] * b[j];
        }
        __syncthreads();
    }
#pragma unroll
    for (int i = 0; i < 4; i++)
#pragma unroll
        for (int j = 0; j < 4; j++)
            d_Wfold[(size_t)(m0 + ty * 4 + i) * G4 + n0 + tx * 4 + j] = acc[i][j];
}

// ================= Kb: bias2 = bridge_b @ w_ih + b_ih + b_hh ; also reset counter ================
__global__ __launch_bounds__(256) void k_bias(const float* __restrict__ bb,
                                              const float* __restrict__ wih,
                                              const float* __restrict__ bih,
                                              const float* __restrict__ bhh) {
    const int g = blockIdx.x * blockDim.x + threadIdx.x;
    if (g == 0) d_ctr = 0u;
    if (g >= G4) return;
    float acc = bih[g] + bhh[g];
    for (int e = 0; e < 512; e++) acc += bb[e] * wih[(size_t)e * G4 + g];
    d_bias2[g] = acc;
}

// ================= K2: gates = gather(emb) @ Wfold + bias2  (tf32 mma) ================
// grid = (G4/64, SEQ); block tile M=64(batch of one timestep) x N=64, K=512
__global__ __launch_bounds__(256) void k_gates(const int* __restrict__ x,
                                               const float* __restrict__ emb) {
    __shared__ float As[64 * 20];   // [64][20] tf32-rounded
    __shared__ float Bs[16 * 68];   // [16][68]
    const int tid  = threadIdx.x;
    const int t    = blockIdx.y;
    const int n0   = blockIdx.x * 64;
    const int lane = tid & 31, wid = tid >> 5;
    const int gid  = lane >> 2, t4 = lane & 3;
    const int wm   = wid >> 2, wn = wid & 3;   // 2x4 warp grid, warp tile 32x16

    const int ar = tid >> 2, ac4 = (tid & 3) * 4;
    const int br = tid >> 4, bc4 = (tid & 15) * 4;
    const int tok = x[(size_t)ar * SEQ + t];
    const float* arow  = emb + (size_t)tok * EMB;
    const float* bbase = d_Wfold + (size_t)br * G4 + n0 + bc4;

    float C[2][2][4] = {};

    for (int k0 = 0; k0 < 512; k0 += 16) {
        float4 av = *(const float4*)(arow + k0 + ac4);
        As[ar * 20 + ac4 + 0] = tf32r(av.x); As[ar * 20 + ac4 + 1] = tf32r(av.y);
        As[ar * 20 + ac4 + 2] = tf32r(av.z); As[ar * 20 + ac4 + 3] = tf32r(av.w);
        float4 bv = *(const float4*)(bbase + (size_t)k0 * G4);
        Bs[br * 68 + bc4 + 0] = tf32r(bv.x); Bs[br * 68 + bc4 + 1] = tf32r(bv.y);
        Bs[br * 68 + bc4 + 2] = tf32r(bv.z); Bs[br * 68 + bc4 + 3] = tf32r(bv.w);
        __syncthreads();
#pragma unroll
        for (int ks = 0; ks < 16; ks += 8) {
            uint32_t a[2][4], b[2][2];
#pragma unroll
            for (int mt = 0; mt < 2; mt++) {
                const int r = wm * 32 + mt * 16 + gid;
                a[mt][0] = __float_as_uint(As[r * 20 + ks + t4]);
                a[mt][1] = __float_as_uint(As[(r + 8) * 20 + ks + t4]);
                a[mt][2] = __float_as_uint(As[r * 20 + ks + 4 + t4]);
                a[mt][3] = __float_as_uint(As[(r + 8) * 20 + ks + 4 + t4]);
            }
#pragma unroll
            for (int nt = 0; nt < 2; nt++) {
                const int c = wn * 16 + nt * 8 + gid;
                b[nt][0] = __float_as_uint(Bs[(ks + t4) * 68 + c]);
                b[nt][1] = __float_as_uint(Bs[(ks + 4 + t4) * 68 + c]);
            }
#pragma unroll
            for (int mt = 0; mt < 2; mt++)
#pragma unroll
                for (int nt = 0; nt < 2; nt++)
                    mma_tf32(C[mt][nt], a[mt][0], a[mt][1], a[mt][2], a[mt][3],
                             b[nt][0], b[nt][1]);
        }
        __syncthreads();
    }

    // epilogue: +bias2, permute into [t][cta][b][32] (col l = gate*8 + hid)
#pragma unroll
    for (int mt = 0; mt < 2; mt++) {
#pragma unroll
        for (int nt = 0; nt < 2; nt++) {
            const int r0 = wm * 32 + mt * 16 + gid;
            const int c0 = n0 + wn * 16 + nt * 8 + t4 * 2;
#pragma unroll
            for (int e = 0; e < 4; e++) {
                const int b = r0 + ((e >> 1) ? 8 : 0);
                const int n = c0 + (e & 1);
                const float v = C[mt][nt][e] + d_bias2[n];
                const int cta   = (n & 1023) >> 3;
                const int local = ((n >> 10) << 3) + (n & 7);
                d_gates[(((size_t)t * NCTA + cta) * BATCH + b) * CPC + local] = v;
            }
        }
    }
}

// ================= K3: persistent LSTM recurrence ================
// 128 CTAs, CTA j owns hidden units [j*8, j*8+8), gate cols ordered [i f g o]x8 in SMEM.
// SMEM: Ws[1024][36] tf32 (144KB) + hs[64][68] (17KB) + gs[64][33] (8.25KB) + cs[512] (2KB)
#define K3_SMEM ((1024 * 36 + 64 * 68 + 64 * 33 + 512) * 4)

__global__ __launch_bounds__(256, 1) void k_lstm(const float* __restrict__ whh) {
    extern __shared__ float sm[];
    float* Ws = sm;                      // [1024][36]
    float* hs = sm + 1024 * 36;          // [64][68]
    float* gs = hs + 64 * 68;            // [64][33]
    float* cs = gs + 64 * 33;            // [512]

    const int tid  = threadIdx.x;
    const int j    = blockIdx.x;
    const int lane = tid & 31, wid = tid >> 5;
    const int gid  = lane >> 2, t4 = lane & 3;
    const int wm   = wid >> 1, wn = wid & 1;   // 4x2 warp grid, warp tile 16x16

    // load w_hh slice (tf32-rounded)
    for (int idx = tid; idx < 1024 * CPC; idx += 256) {
        const int k = idx >> 5, l = idx & 31;
        const int gcol = ((l >> 3) << 10) + j * HPC + (l & 7);
        Ws[k * 36 + l] = tf32r(whh[(size_t)k * G4 + gcol]);
    }
    for (int q = tid; q < 512; q += 256) cs[q] = 0.f;
    __syncthreads();

    for (int t = 0; t < SEQ; t++) {
        if (t > 0) {
            if (tid == 0) {
                volatile unsigned* p = &d_ctr;
                const unsigned tgt = (unsigned)t * NCTA;
                while (*p < tgt) {}
            }
            __syncthreads();
            const float* hprev = d_hbuf[(t - 1) & 1];

            float Cf[2][4] = {};
            for (int kc = 0; kc < 16; kc++) {         // K chunks of 64
#pragma unroll
                for (int i = 0; i < 4; i++) {         // fill hs[64][64] (tf32)
                    const int f4 = tid + i * 256;
                    const int r = f4 >> 4, c4 = (f4 & 15) * 4;
                    float4 v = __ldcg((const float4*)(hprev + (size_t)r * HID + kc * 64 + c4));
                    v.x = tf32r(v.x); v.y = tf32r(v.y); v.z = tf32r(v.z); v.w = tf32r(v.w);
                    *(float4*)(hs + r * 68 + c4) = v;
                }
                __syncthreads();
#pragma unroll
                for (int ks = 0; ks < 64; ks += 8) {
                    const int arow = wm * 16 + gid;
                    const uint32_t a0 = __float_as_uint(hs[arow * 68 + ks + t4]);
                    const uint32_t a1 = __float_as_uint(hs[(arow + 8) * 68 + ks + t4]);
                    const uint32_t a2 = __float_as_uint(hs[arow * 68 + ks + 4 + t4]);
                    const uint32_t a3 = __float_as_uint(hs[(arow + 8) * 68 + ks + 4 + t4]);
                    const int kg = kc * 64 + ks;
#pragma unroll
                    for (int nt = 0; nt < 2; nt++) {
                        const int c = wn * 16 + nt * 8 + gid;
                        const uint32_t b0 = __float_as_uint(Ws[(kg + t4) * 36 + c]);
                        const uint32_t b1 = __float_as_uint(Ws[(kg + 4 + t4) * 36 + c]);
                        mma_tf32(Cf[nt], a0, a1, a2, a3, b0, b1);
                    }
                }
                __syncthreads();
            }
            // scatter C fragments to gs
            {
                const int r0 = wm * 16 + gid;
#pragma unroll
                for (int nt = 0; nt < 2; nt++) {
                    const int c = wn * 16 + nt * 8 + t4 * 2;
                    gs[r0 * 33 + c]           = Cf[nt][0];
                    gs[r0 * 33 + c + 1]       = Cf[nt][1];
                    gs[(r0 + 8) * 33 + c]     = Cf[nt][2];
                    gs[(r0 + 8) * 33 + c + 1] = Cf[nt][3];
                }
            }
            __syncthreads();
        }

        // fused LSTM cell epilogue: 512 (b,hid) pairs, 2 per thread
#pragma unroll
        for (int i = 0; i < 2; i++) {
            const int q = tid + i * 256;
            const int b = q >> 3, hid = q & 7;
            const float* gx = d_gates + (((size_t)t * NCTA + j) * BATCH + b) * CPC;
            float g0 = gx[hid], g1 = gx[8 + hid], g2 = gx[16 + hid], g3 = gx[24 + hid];
            if (t > 0) {
                g0 += gs[b * 33 + hid];
                g1 += gs[b * 33 + 8 + hid];
                g2 += gs[b * 33 + 16 + hid];
                g3 += gs[b * 33 + 24 + hid];
            }
            const float ig = sigf(g0), fg = sigf(g1), gg = tanf_(g2), og = sigf(g3);
            const float c = fg * cs[q] + ig * gg;
            cs[q] = c;
            d_hbuf[t & 1][(size_t)b * HID + j * HPC + hid] = og * tanf_(c);
        }
        __threadfence();
        __syncthreads();
        if (tid == 0) atomicAdd(&d_ctr, 1u);
    }
}

// ================= K4: logits = h_last @ out_w + out_b ================
__global__ void k_out(const float* __restrict__ ow, const float* __restrict__ ob,
                      float* __restrict__ out) {
    const int tid = threadIdx.x;
    if (tid >= 128) return;
    const int b = tid >> 1, n = tid & 1;
    const float* h = d_hbuf[1] + (size_t)b * HID;   // step 511 wrote buffer 1
    float acc = ob[n];
    for (int k = 0; k < HID; k++) acc += h[k] * ow[k * 2 + n];
    out[b * 2 + n] = acc;
}

// ================= launch ================
extern "C" void kernel_launch(void* const* d_in, const int* in_sizes, int n_in,
                              void* d_out, int out_size) {
    const int*   x      = (const int*)  d_in[0];
    const float* embT   = (const float*)d_in[1];
    const float* bw     = (const float*)d_in[2];
    const float* bb     = (const float*)d_in[3];
    const float* wih    = (const float*)d_in[4];
    const float* whh    = (const float*)d_in[5];
    const float* bih    = (const float*)d_in[6];
    const float* bhh    = (const float*)d_in[7];
    const float* ow     = (const float*)d_in[8];
    const float* ob     = (const float*)d_in[9];
    float*       out    = (float*)d_out;

    cudaFuncSetAttribute(k_lstm, cudaFuncAttributeMaxDynamicSharedMemorySize, K3_SMEM);

    k_fold<<<dim3(G4 / 64, EMB / 64), 256>>>(bw, wih);
    k_bias<<<dim3(G4 / 256), 256>>>(bb, wih, bih, bhh);
    k_gates<<<dim3(G4 / 64, SEQ), 256>>>(x, embT);
    k_lstm<<<NCTA, 256, K3_SMEM>>>(whh);
    k_out<<<1, 128>>>(ow, ob, out);
}

// round 5
// speedup vs baseline: 1.0072x; 1.0068x over previous
#include <cuda_runtime.h>
#include <cuda_bf16.h>
#include <cstdint>

// ---------------- problem constants ----------------
#define SEQ   512
#define BATCH 64
#define EMB   512
#define HID   1024
#define G4    4096           // 4*HID
#define NCTA  128            // persistent CTAs for recurrence
#define HPC   8              // hidden units per CTA
#define CPC   32             // gate columns per CTA (4 gates * HPC)
#define KC    128            // recurrence K-chunk
#define NKC   (HID / KC)     // 8 chunks
#define HS_STRIDE 132        // padded row stride (bank-conflict-free)

// ---------------- device scratch (static: no allocations allowed) ----------------
__device__ float             d_Wfold[EMB * G4];                       // 8 MB
__device__ float             d_bias2[G4];
__device__ float             d_gates[(size_t)SEQ * NCTA * BATCH * CPC]; // 512 MB, [t][cta][b][32]
__device__ float             d_hbuf[2][BATCH * HID];                  // double-buffered h
__device__ volatile unsigned d_flags[NCTA];                           // per-CTA step counters

// ---------------- helpers ----------------
__device__ __forceinline__ float tf32r(float x) {
    uint32_t u;
    asm("cvt.rna.tf32.f32 %0, %1;" : "=r"(u) : "f"(x));
    return __uint_as_float(u);
}

__device__ __forceinline__ void mma_tf32(float c[4],
                                         uint32_t a0, uint32_t a1, uint32_t a2, uint32_t a3,
                                         uint32_t b0, uint32_t b1) {
    asm volatile(
        "mma.sync.aligned.m16n8k8.row.col.f32.tf32.tf32.f32 "
        "{%0,%1,%2,%3}, {%4,%5,%6,%7}, {%8,%9}, {%0,%1,%2,%3};\n"
        : "+f"(c[0]), "+f"(c[1]), "+f"(c[2]), "+f"(c[3])
        : "r"(a0), "r"(a1), "r"(a2), "r"(a3), "r"(b0), "r"(b1));
}

__device__ __forceinline__ float sigf(float x) {
    return __fdividef(1.f, 1.f + __expf(-x));
}
__device__ __forceinline__ float tanf_(float x) {
    return __fdividef(2.f, 1.f + __expf(-2.f * x)) - 1.f;
}

__device__ __forceinline__ void cp16(float* s, const float* g) {
    uint32_t sa = (uint32_t)__cvta_generic_to_shared(s);
    asm volatile("cp.async.cg.shared.global [%0], [%1], 16;" :: "r"(sa), "l"(g));
}

// ================= K1: fold  Wfold = bridge_w @ w_ih  (512x4096, K=512, fp32 SIMT) =================
__global__ __launch_bounds__(256) void k_fold(const float* __restrict__ bw,
                                              const float* __restrict__ wih) {
    __shared__ float As[64][17];
    __shared__ float Bs[16][68];
    const int tid = threadIdx.x;
    const int n0 = blockIdx.x * 64, m0 = blockIdx.y * 64;
    const int tx = tid & 15, ty = tid >> 4;
    const int ar = tid >> 2, ac4 = (tid & 3) * 4;
    const int br = tid >> 4, bc4 = (tid & 15) * 4;

    float acc[4][4] = {};
    for (int kc = 0; kc < 512; kc += 16) {
        float4 av = *(const float4*)(bw + (size_t)(m0 + ar) * 512 + kc + ac4);
        As[ar][ac4 + 0] = av.x; As[ar][ac4 + 1] = av.y;
        As[ar][ac4 + 2] = av.z; As[ar][ac4 + 3] = av.w;
        float4 bv = *(const float4*)(wih + (size_t)(kc + br) * G4 + n0 + bc4);
        Bs[br][bc4 + 0] = bv.x; Bs[br][bc4 + 1] = bv.y;
        Bs[br][bc4 + 2] = bv.z; Bs[br][bc4 + 3] = bv.w;
        __syncthreads();
#pragma unroll
        for (int k = 0; k < 16; k++) {
            float a[4], b[4];
#pragma unroll
            for (int i = 0; i < 4; i++) a[i] = As[ty * 4 + i][k];
#pragma unroll
            for (int j = 0; j < 4; j++) b[j] = Bs[k][tx * 4 + j];
#pragma unroll
            for (int i = 0; i < 4; i++)
#pragma unroll
                for (int j = 0; j < 4; j++) acc[i][j] += a[i] * b[j];
        }
        __syncthreads();
    }
#pragma unroll
    for (int i = 0; i < 4; i++)
#pragma unroll
        for (int j = 0; j < 4; j++)
            d_Wfold[(size_t)(m0 + ty * 4 + i) * G4 + n0 + tx * 4 + j] = acc[i][j];
}

// ================= Kb: bias2 = bridge_b @ w_ih + b_ih + b_hh ; reset sync flags ================
__global__ __launch_bounds__(256) void k_bias(const float* __restrict__ bb,
                                              const float* __restrict__ wih,
                                              const float* __restrict__ bih,
                                              const float* __restrict__ bhh) {
    const int g = blockIdx.x * blockDim.x + threadIdx.x;
    if (g < NCTA) d_flags[g] = 0u;
    if (g >= G4) return;
    float acc = bih[g] + bhh[g];
    for (int e = 0; e < 512; e++) acc += bb[e] * wih[(size_t)e * G4 + g];
    d_bias2[g] = acc;
}

// ================= K2: gates = gather(emb) @ Wfold + bias2  (tf32 mma) ================
__global__ __launch_bounds__(256) void k_gates(const int* __restrict__ x,
                                               const float* __restrict__ emb) {
    __shared__ float As[64 * 20];   // [64][20] tf32-rounded
    __shared__ float Bs[16 * 68];   // [16][68]
    const int tid  = threadIdx.x;
    const int t    = blockIdx.y;
    const int n0   = blockIdx.x * 64;
    const int lane = tid & 31, wid = tid >> 5;
    const int gid  = lane >> 2, t4 = lane & 3;
    const int wm   = wid >> 2, wn = wid & 3;   // 2x4 warp grid, warp tile 32x16

    const int ar = tid >> 2, ac4 = (tid & 3) * 4;
    const int br = tid >> 4, bc4 = (tid & 15) * 4;
    const int tok = x[(size_t)ar * SEQ + t];
    const float* arow  = emb + (size_t)tok * EMB;
    const float* bbase = d_Wfold + (size_t)br * G4 + n0 + bc4;

    float C[2][2][4] = {};

    for (int k0 = 0; k0 < 512; k0 += 16) {
        float4 av = *(const float4*)(arow + k0 + ac4);
        As[ar * 20 + ac4 + 0] = tf32r(av.x); As[ar * 20 + ac4 + 1] = tf32r(av.y);
        As[ar * 20 + ac4 + 2] = tf32r(av.z); As[ar * 20 + ac4 + 3] = tf32r(av.w);
        float4 bv = *(const float4*)(bbase + (size_t)k0 * G4);
        Bs[br * 68 + bc4 + 0] = tf32r(bv.x); Bs[br * 68 + bc4 + 1] = tf32r(bv.y);
        Bs[br * 68 + bc4 + 2] = tf32r(bv.z); Bs[br * 68 + bc4 + 3] = tf32r(bv.w);
        __syncthreads();
#pragma unroll
        for (int ks = 0; ks < 16; ks += 8) {
            uint32_t a[2][4], b[2][2];
#pragma unroll
            for (int mt = 0; mt < 2; mt++) {
                const int r = wm * 32 + mt * 16 + gid;
                a[mt][0] = __float_as_uint(As[r * 20 + ks + t4]);
                a[mt][1] = __float_as_uint(As[(r + 8) * 20 + ks + t4]);
                a[mt][2] = __float_as_uint(As[r * 20 + ks + 4 + t4]);
                a[mt][3] = __float_as_uint(As[(r + 8) * 20 + ks + 4 + t4]);
            }
#pragma unroll
            for (int nt = 0; nt < 2; nt++) {
                const int c = wn * 16 + nt * 8 + gid;
                b[nt][0] = __float_as_uint(Bs[(ks + t4) * 68 + c]);
                b[nt][1] = __float_as_uint(Bs[(ks + 4 + t4) * 68 + c]);
            }
#pragma unroll
            for (int mt = 0; mt < 2; mt++)
#pragma unroll
                for (int nt = 0; nt < 2; nt++)
                    mma_tf32(C[mt][nt], a[mt][0], a[mt][1], a[mt][2], a[mt][3],
                             b[nt][0], b[nt][1]);
        }
        __syncthreads();
    }

    // epilogue: +bias2, permute into [t][cta][b][32] (col l = gate*8 + hid)
#pragma unroll
    for (int mt = 0; mt < 2; mt++) {
#pragma unroll
        for (int nt = 0; nt < 2; nt++) {
            const int r0 = wm * 32 + mt * 16 + gid;
            const int c0 = n0 + wn * 16 + nt * 8 + t4 * 2;
#pragma unroll
            for (int e = 0; e < 4; e++) {
                const int b = r0 + ((e >> 1) ? 8 : 0);
                const int n = c0 + (e & 1);
                const float v = C[mt][nt][e] + d_bias2[n];
                const int cta   = (n & 1023) >> 3;
                const int local = ((n >> 10) << 3) + (n & 7);
                d_gates[(((size_t)t * NCTA + cta) * BATCH + b) * CPC + local] = v;
            }
        }
    }
}

// ================= K3: persistent LSTM recurrence (pipelined) ================
// SMEM: Ws[1024][36] (144KB) + hs[2][64][132] (66KB) + gs[64][33] (8.25KB) + cs[512] (2KB)
#define K3_SMEM ((1024 * 36 + 2 * 64 * HS_STRIDE + 64 * 33 + 512) * 4)

__global__ __launch_bounds__(256, 1) void k_lstm(const float* __restrict__ whh) {
    extern __shared__ float sm[];
    float* Ws = sm;                         // [1024][36]
    float* hs = sm + 1024 * 36;             // [2][64][132]
    float* gs = hs + 2 * 64 * HS_STRIDE;    // [64][33]
    float* cs = gs + 64 * 33;               // [512]

    const int tid  = threadIdx.x;
    const int j    = blockIdx.x;
    const int lane = tid & 31, wid = tid >> 5;
    const int gid  = lane >> 2, t4 = lane & 3;
    const int wm   = wid >> 1, wn = wid & 1;   // 4x2 warp grid, warp tile 16x16
    const int arow = wm * 16 + gid;

    // load w_hh slice (tf32-rounded), cols ordered [i f g o] x 8
    for (int idx = tid; idx < 1024 * CPC; idx += 256) {
        const int k = idx >> 5, l = idx & 31;
        const int gcol = ((l >> 3) << 10) + j * HPC + (l & 7);
        Ws[k * 36 + l] = tf32r(whh[(size_t)k * G4 + gcol]);
    }
    for (int q = tid; q < 512; q += 256) cs[q] = 0.f;
    __syncthreads();

    // per-thread epilogue coordinates (q = tid, tid+256)
    const int b0 = tid >> 3,          h0 = tid & 7;
    const int b1 = (tid + 256) >> 3,  h1 = tid & 7;

    for (int t = 0; t < SEQ; t++) {
        // prefetch this step's input-gate preactivations into registers (no deps)
        const float* gx0 = d_gates + (((size_t)t * NCTA + j) * BATCH + b0) * CPC + h0;
        const float* gx1 = d_gates + (((size_t)t * NCTA + j) * BATCH + b1) * CPC + h1;
        float pg0[4], pg1[4];
#pragma unroll
        for (int g = 0; g < 4; g++) { pg0[g] = gx0[g * 8]; pg1[g] = gx1[g * 8]; }

        float Cf[2][4] = {};
        if (t > 0) {
            // wait for all CTAs to finish step t-1 (per-CTA flags, no atomics)
            if (tid < NCTA) {
                while (d_flags[tid] < (unsigned)t) { }
            }
            __syncthreads();
            const float* hprev = d_hbuf[(t - 1) & 1];

            // prologue: issue chunks 0 and 1
#pragma unroll
            for (int p = 0; p < 2; p++) {
                float* dst = hs + p * 64 * HS_STRIDE;
#pragma unroll
                for (int i = 0; i < 8; i++) {
                    const int idx = tid + i * 256;
                    const int r = idx >> 5, c4 = (idx & 31) * 4;
                    cp16(dst + r * HS_STRIDE + c4, hprev + (size_t)r * HID + p * KC + c4);
                }
                asm volatile("cp.async.commit_group;" ::: "memory");
            }

#pragma unroll
            for (int kc = 0; kc < NKC; kc++) {
                if (kc < NKC - 1) asm volatile("cp.async.wait_group 1;" ::: "memory");
                else              asm volatile("cp.async.wait_group 0;" ::: "memory");
                __syncthreads();
                const float* buf = hs + (kc & 1) * 64 * HS_STRIDE;
#pragma unroll
                for (int ks = 0; ks < KC; ks += 8) {
                    const uint32_t a0 = __float_as_uint(buf[arow * HS_STRIDE + ks + t4]);
                    const uint32_t a1 = __float_as_uint(buf[(arow + 8) * HS_STRIDE + ks + t4]);
                    const uint32_t a2 = __float_as_uint(buf[arow * HS_STRIDE + ks + 4 + t4]);
                    const uint32_t a3 = __float_as_uint(buf[(arow + 8) * HS_STRIDE + ks + 4 + t4]);
                    const int kg = kc * KC + ks;
#pragma unroll
                    for (int nt = 0; nt < 2; nt++) {
                        const int c = wn * 16 + nt * 8 + gid;
                        const uint32_t bb0 = __float_as_uint(Ws[(kg + t4) * 36 + c]);
                        const uint32_t bb1 = __float_as_uint(Ws[(kg + 4 + t4) * 36 + c]);
                        mma_tf32(Cf[nt], a0, a1, a2, a3, bb0, bb1);
                    }
                }
                __syncthreads();
                if (kc < NKC - 2) {
                    float* dst = hs + (kc & 1) * 64 * HS_STRIDE;
#pragma unroll
                    for (int i = 0; i < 8; i++) {
                        const int idx = tid + i * 256;
                        const int r = idx >> 5, c4 = (idx & 31) * 4;
                        cp16(dst + r * HS_STRIDE + c4,
                             hprev + (size_t)r * HID + (kc + 2) * KC + c4);
                    }
                    asm volatile("cp.async.commit_group;" ::: "memory");
                }
            }

            // scatter C fragments to gs
            {
                const int r0 = wm * 16 + gid;
#pragma unroll
                for (int nt = 0; nt < 2; nt++) {
                    const int c = wn * 16 + nt * 8 + t4 * 2;
                    gs[r0 * 33 + c]           = Cf[nt][0];
                    gs[r0 * 33 + c + 1]       = Cf[nt][1];
                    gs[(r0 + 8) * 33 + c]     = Cf[nt][2];
                    gs[(r0 + 8) * 33 + c + 1] = Cf[nt][3];
                }
            }
            __syncthreads();
        }

        // fused LSTM cell epilogue: 512 (b,hid) pairs, 2 per thread
        float* hout = d_hbuf[t & 1];
        {
            float g0 = pg0[0], g1 = pg0[1], g2 = pg0[2], g3 = pg0[3];
            if (t > 0) {
                g0 += gs[b0 * 33 + h0];
                g1 += gs[b0 * 33 + 8 + h0];
                g2 += gs[b0 * 33 + 16 + h0];
                g3 += gs[b0 * 33 + 24 + h0];
            }
            const float ig = sigf(g0), fg = sigf(g1), gg = tanf_(g2), og = sigf(g3);
            const float c = fg * cs[tid] + ig * gg;
            cs[tid] = c;
            hout[(size_t)b0 * HID + j * HPC + h0] = og * tanf_(c);
        }
        {
            float g0 = pg1[0], g1 = pg1[1], g2 = pg1[2], g3 = pg1[3];
            if (t > 0) {
                g0 += gs[b1 * 33 + h1];
                g1 += gs[b1 * 33 + 8 + h1];
                g2 += gs[b1 * 33 + 16 + h1];
                g3 += gs[b1 * 33 + 24 + h1];
            }
            const float ig = sigf(g0), fg = sigf(g1), gg = tanf_(g2), og = sigf(g3);
            const float c = fg * cs[tid + 256] + ig * gg;
            cs[tid + 256] = c;
            hout[(size_t)b1 * HID + j * HPC + h1] = og * tanf_(c);
        }
        __threadfence();
        __syncthreads();
        if (tid == 0) d_flags[j] = (unsigned)(t + 1);
    }
}

// ================= K4: logits = h_last @ out_w + out_b ================
__global__ void k_out(const float* __restrict__ ow, const float* __restrict__ ob,
                      float* __restrict__ out) {
    const int tid = threadIdx.x;
    if (tid >= 128) return;
    const int b = tid >> 1, n = tid & 1;
    const float* h = d_hbuf[1] + (size_t)b * HID;   // step 511 wrote buffer 1
    float acc = ob[n];
    for (int k = 0; k < HID; k++) acc += h[k] * ow[k * 2 + n];
    out[b * 2 + n] = acc;
}

// ================= launch ================
extern "C" void kernel_launch(void* const* d_in, const int* in_sizes, int n_in,
                              void* d_out, int out_size) {
    const int*   x      = (const int*)  d_in[0];
    const float* embT   = (const float*)d_in[1];
    const float* bw     = (const float*)d_in[2];
    const float* bb     = (const float*)d_in[3];
    const float* wih    = (const float*)d_in[4];
    const float* whh    = (const float*)d_in[5];
    const float* bih    = (const float*)d_in[6];
    const float* bhh    = (const float*)d_in[7];
    const float* ow     = (const float*)d_in[8];
    const float* ob     = (const float*)d_in[9];
    float*       out    = (float*)d_out;

    cudaFuncSetAttribute(k_lstm, cudaFuncAttributeMaxDynamicSharedMemorySize, K3_SMEM);

    k_fold<<<dim3(G4 / 64, EMB / 64), 256>>>(bw, wih);
    k_bias<<<dim3(G4 / 256), 256>>>(bb, wih, bih, bhh);
    k_gates<<<dim3(G4 / 64, SEQ), 256>>>(x, embT);
    k_lstm<<<NCTA, 256, K3_SMEM>>>(whh);
    k_out<<<1, 128>>>(ow, ob, out);
}

// round 7
// speedup vs baseline: 1.1630x; 1.1547x over previous
#include <cuda_runtime.h>
#include <cuda_bf16.h>
#include <cstdint>

// ---------------- problem constants ----------------
#define SEQ   512
#define BATCH 64
#define EMB   512
#define HID   1024
#define G4    4096
#define NCTA  128
#define HPC   8
#define CPC   32

// ---------------- device scratch ----------------
__device__ float             d_WfoldT[(size_t)G4 * EMB];                // 8 MB, [n][k] transposed+perm
__device__ float             d_bias2[G4];
__device__ float             d_gates[(size_t)SEQ * NCTA * BATCH * CPC]; // 512 MB [t][cta][b][32]
__device__ float             d_hbuf[2][BATCH * HID];                    // k-permuted storage
__device__ volatile unsigned d_flags[NCTA];

// ---------------- helpers ----------------
__device__ __forceinline__ int p8(int e) { return ((e & 3) << 1) | (e >> 2); }

__device__ __forceinline__ float tf32r(float x) {
    uint32_t u;
    asm("cvt.rna.tf32.f32 %0, %1;" : "=r"(u) : "f"(x));
    return __uint_as_float(u);
}
__device__ __forceinline__ float sigf(float x) { return __fdividef(1.f, 1.f + __expf(-x)); }
__device__ __forceinline__ float tanf_(float x) { return __fdividef(2.f, 1.f + __expf(-2.f * x)) - 1.f; }

__device__ __forceinline__ uint32_t smem_u32(const void* p) {
    uint32_t a;
    asm("{ .reg .u64 t; cvta.to.shared.u64 t, %1; cvt.u32.u64 %0, t; }" : "=r"(a) : "l"(p));
    return a;
}
__device__ __forceinline__ void cp16_sm(uint32_t s, const float* g) {
    asm volatile("cp.async.cg.shared.global [%0], [%1], 16;" :: "r"(s), "l"(g));
}
__device__ __forceinline__ void mma_tf32(float c[4],
                                         uint32_t a0, uint32_t a1, uint32_t a2, uint32_t a3,
                                         uint32_t b0, uint32_t b1) {
    asm volatile(
        "mma.sync.aligned.m16n8k8.row.col.f32.tf32.tf32.f32 "
        "{%0,%1,%2,%3}, {%4,%5,%6,%7}, {%8,%9}, {%0,%1,%2,%3};\n"
        : "+f"(c[0]), "+f"(c[1]), "+f"(c[2]), "+f"(c[3])
        : "r"(a0), "r"(a1), "r"(a2), "r"(a3), "r"(b0), "r"(b1));
}

// ================= K1: fold  WfoldT[n][perm(k)] = (bridge_w @ w_ih)[k][n] =================
__global__ __launch_bounds__(256) void k_fold(const float* __restrict__ bw,
                                              const float* __restrict__ wih) {
    __shared__ float As[64][17];
    __shared__ float Bs[16][68];
    const int tid = threadIdx.x;
    const int n0 = blockIdx.x * 64, m0 = blockIdx.y * 64;
    const int tx = tid & 15, ty = tid >> 4;
    const int ar = tid >> 2, ac4 = (tid & 3) * 4;
    const int br = tid >> 4, bc4 = (tid & 15) * 4;

    float acc[4][4] = {};
    for (int kc = 0; kc < 512; kc += 16) {
        float4 av = *(const float4*)(bw + (size_t)(m0 + ar) * 512 + kc + ac4);
        As[ar][ac4 + 0] = av.x; As[ar][ac4 + 1] = av.y;
        As[ar][ac4 + 2] = av.z; As[ar][ac4 + 3] = av.w;
        float4 bv = *(const float4*)(wih + (size_t)(kc + br) * G4 + n0 + bc4);
        Bs[br][bc4 + 0] = bv.x; Bs[br][bc4 + 1] = bv.y;
        Bs[br][bc4 + 2] = bv.z; Bs[br][bc4 + 3] = bv.w;
        __syncthreads();
#pragma unroll
        for (int k = 0; k < 16; k++) {
            float a[4], b[4];
#pragma unroll
            for (int i = 0; i < 4; i++) a[i] = As[ty * 4 + i][k];
#pragma unroll
            for (int j = 0; j < 4; j++) b[j] = Bs[k][tx * 4 + j];
#pragma unroll
            for (int i = 0; i < 4; i++)
#pragma unroll
                for (int j = 0; j < 4; j++) acc[i][j] += a[i] * b[j];
        }
        __syncthreads();
    }
#pragma unroll
    for (int i = 0; i < 4; i++) {
        const int m = m0 + ty * 4 + i;
        const int mp = (m & ~7) | p8(m & 7);
#pragma unroll
        for (int j = 0; j < 4; j++)
            d_WfoldT[(size_t)(n0 + tx * 4 + j) * 512 + mp] = tf32r(acc[i][j]);
    }
}

// ================= Kb: bias2 ; reset flags ================
__global__ __launch_bounds__(256) void k_bias(const float* __restrict__ bb,
                                              const float* __restrict__ wih,
                                              const float* __restrict__ bih,
                                              const float* __restrict__ bhh) {
    const int g = blockIdx.x * blockDim.x + threadIdx.x;
    if (g < NCTA) d_flags[g] = 0u;
    if (g >= G4) return;
    float acc = bih[g] + bhh[g];
    for (int e = 0; e < 512; e++) acc += bb[e] * wih[(size_t)e * G4 + g];
    d_bias2[g] = acc;
}

// ================= K2: gates = gather(emb) @ Wfold + bias2 ================
// M=128 (2 timesteps), N=64, K=512 in 16 blocks of 32, cp.async double-buffered B,
// 8 warps of 32x32 tiles, vectorized LDS via K pair-permutation.
#define AS_STR 36
#define KG_SMEM ((2 * 128 * AS_STR + 2 * 64 * AS_STR + 64) * 4)

__global__ __launch_bounds__(256, 2) void k_gates(const int* __restrict__ x,
                                                  const float* __restrict__ emb) {
    extern __shared__ float sg[];
    float* As = sg;                          // [2][128][36]
    float* Bs = sg + 2 * 128 * AS_STR;       // [2][64][36]
    float* bias_s = Bs + 2 * 64 * AS_STR;    // [64]
    const uint32_t sbB = smem_u32(Bs);

    const int tid  = threadIdx.x;
    const int t0   = blockIdx.y * 2;
    const int n0   = blockIdx.x * 64;
    const int lane = tid & 31, wid = tid >> 5;
    const int gid  = lane >> 2, t4 = lane & 3;
    const int wm   = wid >> 1, wn = wid & 1;

    if (tid < 64) bias_s[tid] = d_bias2[n0 + tid];

    const int r    = tid >> 1, half = tid & 1;
    const int tokb = r & 63, tokt = t0 + (r >> 6);
    const float* arow = emb + (size_t)x[(size_t)tokb * SEQ + tokt] * EMB;

    float4 RA[2][2];
#define LDGA(KB) do { \
    const int _e0 = (KB) * 32 + half * 16; \
    RA[0][0] = *(const float4*)(arow + _e0);      RA[0][1] = *(const float4*)(arow + _e0 + 4); \
    RA[1][0] = *(const float4*)(arow + _e0 + 8);  RA[1][1] = *(const float4*)(arow + _e0 + 12); \
} while (0)
#define STSA(BUF) do { \
    float* _dst = As + (BUF) * 128 * AS_STR + r * AS_STR + half * 16; \
    _Pragma("unroll") for (int _g = 0; _g < 2; _g++) { \
        const float* _f0 = (const float*)&RA[_g][0]; \
        const float* _f1 = (const float*)&RA[_g][1]; \
        _Pragma("unroll") for (int _i = 0; _i < 4; _i++) { \
            float2 _pr; _pr.x = tf32r(_f0[_i]); _pr.y = tf32r(_f1[_i]); \
            *(float2*)(_dst + _g * 8 + 2 * _i) = _pr; \
        } \
    } \
} while (0)
#define CPB(KB, BUF) do { \
    _Pragma("unroll") for (int _i = 0; _i < 2; _i++) { \
        const int _idx = tid + _i * 256; \
        const int _n = _idx >> 3, _f = _idx & 7; \
        cp16_sm(sbB + ((BUF) * 64 * AS_STR + _n * AS_STR + _f * 4) * 4, \
                d_WfoldT + (size_t)(n0 + _n) * 512 + (KB) * 32 + _f * 4); \
    } \
    asm volatile("cp.async.commit_group;" ::: "memory"); \
} while (0)

    float C[2][4][4] = {};

    LDGA(0); CPB(0, 0); STSA(0);
    LDGA(1); CPB(1, 1); STSA(1);
    LDGA(2);

    for (int kb = 0; kb < 16; kb++) {
        if (kb < 15) asm volatile("cp.async.wait_group 1;" ::: "memory");
        else         asm volatile("cp.async.wait_group 0;" ::: "memory");
        __syncthreads();
        {
            const float* Ab = As + (kb & 1) * 128 * AS_STR;
            const float* Bb = Bs + (kb & 1) * 64 * AS_STR;
#pragma unroll
            for (int ks = 0; ks < 4; ks++) {
                float2 au[2], av[2];
#pragma unroll
                for (int mf = 0; mf < 2; mf++) {
                    const int rr = wm * 32 + mf * 16 + gid;
                    au[mf] = *(const float2*)(Ab + rr * AS_STR + ks * 8 + 2 * t4);
                    av[mf] = *(const float2*)(Ab + (rr + 8) * AS_STR + ks * 8 + 2 * t4);
                }
                uint32_t bu[4][2];
#pragma unroll
                for (int nf = 0; nf < 4; nf++) {
                    float2 bv = *(const float2*)(Bb + (wn * 32 + nf * 8 + gid) * AS_STR + ks * 8 + 2 * t4);
                    bu[nf][0] = __float_as_uint(bv.x);
                    bu[nf][1] = __float_as_uint(bv.y);
                }
#pragma unroll
                for (int mf = 0; mf < 2; mf++)
#pragma unroll
                    for (int nf = 0; nf < 4; nf++)
                        mma_tf32(C[mf][nf],
                                 __float_as_uint(au[mf].x), __float_as_uint(av[mf].x),
                                 __float_as_uint(au[mf].y), __float_as_uint(av[mf].y),
                                 bu[nf][0], bu[nf][1]);
            }
        }
        __syncthreads();
        if (kb + 2 < 16) {
            STSA(kb & 1);
            CPB(kb + 2, kb & 1);
            if (kb + 3 < 16) LDGA(kb + 3);
        }
    }

    // epilogue: +bias2, permute into [t][cta][b][32]
#pragma unroll
    for (int mf = 0; mf < 2; mf++) {
#pragma unroll
        for (int nf = 0; nf < 4; nf++) {
            const int cc = wn * 32 + nf * 8 + 2 * t4;
            const int n  = n0 + cc;
            const int cta = (n & 1023) >> 3;
            const int loc = ((n >> 10) << 3) + (n & 7);
            const float bz0 = bias_s[cc], bz1 = bias_s[cc + 1];
#pragma unroll
            for (int e = 0; e < 2; e++) {
                const int rr = wm * 32 + mf * 16 + gid + e * 8;
                const int b = rr & 63, tt = t0 + (rr >> 6);
                float2 v;
                v.x = C[mf][nf][2 * e]     + bz0;
                v.y = C[mf][nf][2 * e + 1] + bz1;
                *(float2*)&d_gates[(((size_t)tt * NCTA + cta) * BATCH + b) * CPC + loc] = v;
            }
        }
    }
#undef LDGA
#undef STSA
#undef CPB
}

// ================= K3: persistent LSTM recurrence (32x32 warp tiles, K-split) ================
// SMEM: Ws[32][1032] (132KB) | hs[2][64][132] (66KB, gs[8][32][34] overlays it)
#define WS_STR 1032
#define HS_STR 132
#define GS_STR 34
#define HS_OFF (32 * WS_STR)
#define HS_BUF (64 * HS_STR)
#define K3_SMEM ((HS_OFF + 2 * HS_BUF) * 4)   // 199680 bytes

__global__ __launch_bounds__(256, 1) void k_lstm(const float* __restrict__ whh) {
    extern __shared__ float sm[];
    float* Ws = sm;                 // [32][1032]
    float* hs = sm + HS_OFF;        // [2][64][132]
    float* gs = hs;                 // overlay [8][32][34]
    const uint32_t sbH = smem_u32(hs);

    const int tid  = threadIdx.x;
    const int j    = blockIdx.x;
    const int lane = tid & 31, wid = tid >> 5;
    const int gid  = lane >> 2, t4 = lane & 3;
    const int kq   = wid >> 1, wm = wid & 1;   // K-quarter, M-half

    // build Ws[n][perm(k)] = tf32(whh[k][gcol(n)])
    for (int idx = tid; idx < 32 * HID; idx += 256) {
        const int n = idx >> 10, k = idx & 1023;
        const int gcol = ((n >> 3) << 10) + j * HPC + (n & 7);
        Ws[n * WS_STR + (k & ~7) + p8(k & 7)] = tf32r(whh[(size_t)k * G4 + gcol]);
    }
    __syncthreads();

    const int b0 = tid >> 3, h0 = tid & 7, b1 = b0 + 32;
    float creg0 = 0.f, creg1 = 0.f;

    for (int t = 0; t < SEQ; t++) {
        // prefetch input-gate preactivations
        const float* gx = d_gates + (((size_t)t * NCTA + j) * BATCH) * CPC;
        float pg0[4], pg1[4];
#pragma unroll
        for (int g = 0; g < 4; g++) {
            pg0[g] = gx[b0 * CPC + g * 8 + h0];
            pg1[g] = gx[b1 * CPC + g * 8 + h0];
        }

        float Cf[2][4][4] = {};
        if (t > 0) {
            if (tid < NCTA) { while (d_flags[tid] < (unsigned)t) { } }
            __syncthreads();
            const float* hp = d_hbuf[(t - 1) & 1];

#define STAGE(BUF, CH) do { \
    _Pragma("unroll") for (int _i = 0; _i < 8; _i++) { \
        const int _idx = tid + _i * 256; \
        const int _r = _idx >> 5, _f = _idx & 31; \
        cp16_sm(sbH + ((BUF) * HS_BUF + _r * HS_STR + _f * 4) * 4, \
                hp + (size_t)_r * HID + (CH) * 128 + _f * 4); \
    } \
    asm volatile("cp.async.commit_group;" ::: "memory"); \
} while (0)

            STAGE(0, 0);
            STAGE(1, 1);
#pragma unroll
            for (int c = 0; c < 8; c++) {
                if (c < 7) asm volatile("cp.async.wait_group 1;" ::: "memory");
                else       asm volatile("cp.async.wait_group 0;" ::: "memory");
                __syncthreads();
                {
                    const float* buf = hs + (c & 1) * HS_BUF;
                    const float* Wb  = Ws + c * 128 + kq * 32;
#pragma unroll
                    for (int ks = 0; ks < 4; ks++) {
                        const int cb = kq * 32 + ks * 8;
                        float2 au[2], av[2];
#pragma unroll
                        for (int mf = 0; mf < 2; mf++) {
                            const int rr = wm * 32 + mf * 16 + gid;
                            au[mf] = *(const float2*)(buf + rr * HS_STR + cb + 2 * t4);
                            av[mf] = *(const float2*)(buf + (rr + 8) * HS_STR + cb + 2 * t4);
                        }
                        uint32_t bu[4][2];
#pragma unroll
                        for (int nf = 0; nf < 4; nf++) {
                            float2 bv = *(const float2*)(Wb + (nf * 8 + gid) * WS_STR + ks * 8 + 2 * t4);
                            bu[nf][0] = __float_as_uint(bv.x);
                            bu[nf][1] = __float_as_uint(bv.y);
                        }
#pragma unroll
                        for (int mf = 0; mf < 2; mf++)
#pragma unroll
                            for (int nf = 0; nf < 4; nf++)
                                mma_tf32(Cf[mf][nf],
                                         __float_as_uint(au[mf].x), __float_as_uint(av[mf].x),
                                         __float_as_uint(au[mf].y), __float_as_uint(av[mf].y),
                                         bu[nf][0], bu[nf][1]);
                    }
                }
                __syncthreads();
                if (c + 2 < 8) STAGE(c & 1, c + 2);
            }
#undef STAGE

            // stash partial C to gs[warp][32][34]
            const int gbase = wid * 32 * GS_STR;
#pragma unroll
            for (int mf = 0; mf < 2; mf++) {
                const int rl = mf * 16 + gid;
#pragma unroll
                for (int nf = 0; nf < 4; nf++) {
                    float2 v0, v1;
                    v0.x = Cf[mf][nf][0]; v0.y = Cf[mf][nf][1];
                    v1.x = Cf[mf][nf][2]; v1.y = Cf[mf][nf][3];
                    *(float2*)&gs[gbase + rl * GS_STR + nf * 8 + 2 * t4]       = v0;
                    *(float2*)&gs[gbase + (rl + 8) * GS_STR + nf * 8 + 2 * t4] = v1;
                }
            }
            __syncthreads();
        }

        // fused LSTM cell: 2 (b,hid) pairs per thread; reduce 4 K-quarter partials
        float a0[4], a1[4];
#pragma unroll
        for (int g = 0; g < 4; g++) { a0[g] = pg0[g]; a1[g] = pg1[g]; }
        if (t > 0) {
#pragma unroll
            for (int q = 0; q < 4; q++) {
                const int base0 = (2 * q + 0) * 32 * GS_STR + (b0 & 31) * GS_STR;
                const int base1 = (2 * q + 1) * 32 * GS_STR + (b1 & 31) * GS_STR;
#pragma unroll
                for (int g = 0; g < 4; g++) {
                    a0[g] += gs[base0 + g * 8 + h0];
                    a1[g] += gs[base1 + g * 8 + h0];
                }
            }
        }
        float* hout = d_hbuf[t & 1];
        {
            const float gi = sigf(a0[0]), gf = sigf(a0[1]), gg = tanf_(a0[2]), go = sigf(a0[3]);
            creg0 = gf * creg0 + gi * gg;
            hout[(size_t)b0 * HID + j * HPC + p8(h0)] = go * tanf_(creg0);
        }
        {
            const float gi = sigf(a1[0]), gf = sigf(a1[1]), gg = tanf_(a1[2]), go = sigf(a1[3]);
            creg1 = gf * creg1 + gi * gg;
            hout[(size_t)b1 * HID + j * HPC + p8(h0)] = go * tanf_(creg1);
        }
        __threadfence();
        __syncthreads();
        if (tid == 0) d_flags[j] = (unsigned)(t + 1);
    }
}

// ================= K4: logits (un-permute h) ================
__global__ void k_out(const float* __restrict__ ow, const float* __restrict__ ob,
                      float* __restrict__ out) {
    const int tid = threadIdx.x;
    if (tid >= 128) return;
    const int b = tid >> 1, n = tid & 1;
    const float* h = d_hbuf[1] + (size_t)b * HID;   // step 511 wrote buffer 1
    float acc = ob[n];
    for (int c = 0; c < HID; c++) {
        const int phys = (c & ~7) + p8(c & 7);
        acc += h[phys] * ow[c * 2 + n];
    }
    out[b * 2 + n] = acc;
}

// ================= launch ================
extern "C" void kernel_launch(void* const* d_in, const int* in_sizes, int n_in,
                              void* d_out, int out_size) {
    const int*   x    = (const int*)  d_in[0];
    const float* embT = (const float*)d_in[1];
    const float* bw   = (const float*)d_in[2];
    const float* bb   = (const float*)d_in[3];
    const float* wih  = (const float*)d_in[4];
    const float* whh  = (const float*)d_in[5];
    const float* bih  = (const float*)d_in[6];
    const float* bhh  = (const float*)d_in[7];
    const float* ow   = (const float*)d_in[8];
    const float* ob   = (const float*)d_in[9];
    float*       out  = (float*)d_out;

    cudaFuncSetAttribute(k_gates, cudaFuncAttributeMaxDynamicSharedMemorySize, KG_SMEM);
    cudaFuncSetAttribute(k_lstm,  cudaFuncAttributeMaxDynamicSharedMemorySize, K3_SMEM);

    k_fold<<<dim3(G4 / 64, EMB / 64), 256>>>(bw, wih);
    k_bias<<<dim3(G4 / 256), 256>>>(bb, wih, bih, bhh);
    k_gates<<<dim3(G4 / 64, SEQ / 2), 256, KG_SMEM>>>(x, embT);
    k_lstm<<<NCTA, 256, K3_SMEM>>>(whh);
    k_out<<<1, 128>>>(ow, ob, out);
}

// round 8
// speedup vs baseline: 1.1983x; 1.0303x over previous
#include <cuda_runtime.h>
#include <cuda_bf16.h>
#include <cstdint>

// ---------------- problem constants ----------------
#define SEQ   512
#define BATCH 64
#define EMB   512
#define HID   1024
#define G4    4096
#define NCTA  128
#define HPC   8
#define CPC   32

// ---------------- device scratch ----------------
__device__ float             d_WfoldT[(size_t)G4 * EMB];                // 8 MB, [n][k] transposed+perm
__device__ float             d_bias2[G4];
__device__ float             d_gates[(size_t)SEQ * NCTA * BATCH * CPC]; // 512 MB [t][cta][b][32]
__device__ float             d_hbuf[2][BATCH * HID];                    // k-permuted storage
__device__ volatile unsigned d_flags[NCTA];

// ---------------- helpers ----------------
__device__ __forceinline__ int p8(int e) { return ((e & 3) << 1) | (e >> 2); }

__device__ __forceinline__ float tf32r(float x) {
    uint32_t u;
    asm("cvt.rna.tf32.f32 %0, %1;" : "=r"(u) : "f"(x));
    return __uint_as_float(u);
}
__device__ __forceinline__ float sigf(float x) { return __fdividef(1.f, 1.f + __expf(-x)); }
__device__ __forceinline__ float tanf_(float x) { return __fdividef(2.f, 1.f + __expf(-2.f * x)) - 1.f; }

__device__ __forceinline__ uint32_t smem_u32(const void* p) {
    uint32_t a;
    asm("{ .reg .u64 t; cvta.to.shared.u64 t, %1; cvt.u32.u64 %0, t; }" : "=r"(a) : "l"(p));
    return a;
}
__device__ __forceinline__ void cp16_sm(uint32_t s, const float* g) {
    asm volatile("cp.async.cg.shared.global [%0], [%1], 16;" :: "r"(s), "l"(g));
}
__device__ __forceinline__ void mma_tf32(float c[4],
                                         uint32_t a0, uint32_t a1, uint32_t a2, uint32_t a3,
                                         uint32_t b0, uint32_t b1) {
    asm volatile(
        "mma.sync.aligned.m16n8k8.row.col.f32.tf32.tf32.f32 "
        "{%0,%1,%2,%3}, {%4,%5,%6,%7}, {%8,%9}, {%0,%1,%2,%3};\n"
        : "+f"(c[0]), "+f"(c[1]), "+f"(c[2]), "+f"(c[3])
        : "r"(a0), "r"(a1), "r"(a2), "r"(a3), "r"(b0), "r"(b1));
}

// ================= K1: fold  WfoldT[n][perm(k)] = (bridge_w @ w_ih)[k][n] =================
__global__ __launch_bounds__(256) void k_fold(const float* __restrict__ bw,
                                              const float* __restrict__ wih) {
    __shared__ float As[64][17];
    __shared__ float Bs[16][68];
    const int tid = threadIdx.x;
    const int n0 = blockIdx.x * 64, m0 = blockIdx.y * 64;
    const int tx = tid & 15, ty = tid >> 4;
    const int ar = tid >> 2, ac4 = (tid & 3) * 4;
    const int br = tid >> 4, bc4 = (tid & 15) * 4;

    float acc[4][4] = {};
    for (int kc = 0; kc < 512; kc += 16) {
        float4 av = *(const float4*)(bw + (size_t)(m0 + ar) * 512 + kc + ac4);
        As[ar][ac4 + 0] = av.x; As[ar][ac4 + 1] = av.y;
        As[ar][ac4 + 2] = av.z; As[ar][ac4 + 3] = av.w;
        float4 bv = *(const float4*)(wih + (size_t)(kc + br) * G4 + n0 + bc4);
        Bs[br][bc4 + 0] = bv.x; Bs[br][bc4 + 1] = bv.y;
        Bs[br][bc4 + 2] = bv.z; Bs[br][bc4 + 3] = bv.w;
        __syncthreads();
#pragma unroll
        for (int k = 0; k < 16; k++) {
            float a[4], b[4];
#pragma unroll
            for (int i = 0; i < 4; i++) a[i] = As[ty * 4 + i][k];
#pragma unroll
            for (int j = 0; j < 4; j++) b[j] = Bs[k][tx * 4 + j];
#pragma unroll
            for (int i = 0; i < 4; i++)
#pragma unroll
                for (int j = 0; j < 4; j++) acc[i][j] += a[i] * b[j];
        }
        __syncthreads();
    }
#pragma unroll
    for (int i = 0; i < 4; i++) {
        const int m = m0 + ty * 4 + i;
        const int mp = (m & ~7) | p8(m & 7);
#pragma unroll
        for (int j = 0; j < 4; j++)
            d_WfoldT[(size_t)(n0 + tx * 4 + j) * 512 + mp] = tf32r(acc[i][j]);
    }
}

// ================= Kb: bias2 ; reset flags ================
__global__ __launch_bounds__(256) void k_bias(const float* __restrict__ bb,
                                              const float* __restrict__ wih,
                                              const float* __restrict__ bih,
                                              const float* __restrict__ bhh) {
    const int g = blockIdx.x * blockDim.x + threadIdx.x;
    if (g < NCTA) d_flags[g] = 0u;
    if (g >= G4) return;
    float acc = bih[g] + bhh[g];
    for (int e = 0; e < 512; e++) acc += bb[e] * wih[(size_t)e * G4 + g];
    d_bias2[g] = acc;
}

// ================= K2: gates = gather(emb) @ Wfold + bias2 ================
#define AS_STR 36
#define KG_SMEM ((2 * 128 * AS_STR + 2 * 64 * AS_STR + 64) * 4)

__global__ __launch_bounds__(256, 2) void k_gates(const int* __restrict__ x,
                                                  const float* __restrict__ emb) {
    extern __shared__ float sg[];
    float* As = sg;                          // [2][128][36]
    float* Bs = sg + 2 * 128 * AS_STR;       // [2][64][36]
    float* bias_s = Bs + 2 * 64 * AS_STR;    // [64]
    const uint32_t sbB = smem_u32(Bs);

    const int tid  = threadIdx.x;
    const int t0   = blockIdx.y * 2;
    const int n0   = blockIdx.x * 64;
    const int lane = tid & 31, wid = tid >> 5;
    const int gid  = lane >> 2, t4 = lane & 3;
    const int wm   = wid >> 1, wn = wid & 1;

    if (tid < 64) bias_s[tid] = d_bias2[n0 + tid];

    const int r    = tid >> 1, half = tid & 1;
    const int tokb = r & 63, tokt = t0 + (r >> 6);
    const float* arow = emb + (size_t)x[(size_t)tokb * SEQ + tokt] * EMB;

    float4 RA[2][2];
#define LDGA(KB) do { \
    const int _e0 = (KB) * 32 + half * 16; \
    RA[0][0] = *(const float4*)(arow + _e0);      RA[0][1] = *(const float4*)(arow + _e0 + 4); \
    RA[1][0] = *(const float4*)(arow + _e0 + 8);  RA[1][1] = *(const float4*)(arow + _e0 + 12); \
} while (0)
#define STSA(BUF) do { \
    float* _dst = As + (BUF) * 128 * AS_STR + r * AS_STR + half * 16; \
    _Pragma("unroll") for (int _g = 0; _g < 2; _g++) { \
        const float* _f0 = (const float*)&RA[_g][0]; \
        const float* _f1 = (const float*)&RA[_g][1]; \
        _Pragma("unroll") for (int _i = 0; _i < 4; _i++) { \
            float2 _pr; _pr.x = tf32r(_f0[_i]); _pr.y = tf32r(_f1[_i]); \
            *(float2*)(_dst + _g * 8 + 2 * _i) = _pr; \
        } \
    } \
} while (0)
#define CPB(KB, BUF) do { \
    _Pragma("unroll") for (int _i = 0; _i < 2; _i++) { \
        const int _idx = tid + _i * 256; \
        const int _n = _idx >> 3, _f = _idx & 7; \
        cp16_sm(sbB + ((BUF) * 64 * AS_STR + _n * AS_STR + _f * 4) * 4, \
                d_WfoldT + (size_t)(n0 + _n) * 512 + (KB) * 32 + _f * 4); \
    } \
    asm volatile("cp.async.commit_group;" ::: "memory"); \
} while (0)

    float C[2][4][4] = {};

    LDGA(0); CPB(0, 0); STSA(0);
    LDGA(1); CPB(1, 1); STSA(1);
    LDGA(2);

    for (int kb = 0; kb < 16; kb++) {
        if (kb < 15) asm volatile("cp.async.wait_group 1;" ::: "memory");
        else         asm volatile("cp.async.wait_group 0;" ::: "memory");
        __syncthreads();
        {
            const float* Ab = As + (kb & 1) * 128 * AS_STR;
            const float* Bb = Bs + (kb & 1) * 64 * AS_STR;
#pragma unroll
            for (int ks = 0; ks < 4; ks++) {
                float2 au[2], av[2];
#pragma unroll
                for (int mf = 0; mf < 2; mf++) {
                    const int rr = wm * 32 + mf * 16 + gid;
                    au[mf] = *(const float2*)(Ab + rr * AS_STR + ks * 8 + 2 * t4);
                    av[mf] = *(const float2*)(Ab + (rr + 8) * AS_STR + ks * 8 + 2 * t4);
                }
                uint32_t bu[4][2];
#pragma unroll
                for (int nf = 0; nf < 4; nf++) {
                    float2 bv = *(const float2*)(Bb + (wn * 32 + nf * 8 + gid) * AS_STR + ks * 8 + 2 * t4);
                    bu[nf][0] = __float_as_uint(bv.x);
                    bu[nf][1] = __float_as_uint(bv.y);
                }
#pragma unroll
                for (int mf = 0; mf < 2; mf++)
#pragma unroll
                    for (int nf = 0; nf < 4; nf++)
                        mma_tf32(C[mf][nf],
                                 __float_as_uint(au[mf].x), __float_as_uint(av[mf].x),
                                 __float_as_uint(au[mf].y), __float_as_uint(av[mf].y),
                                 bu[nf][0], bu[nf][1]);
            }
        }
        __syncthreads();
        if (kb + 2 < 16) {
            STSA(kb & 1);
            CPB(kb + 2, kb & 1);
            if (kb + 3 < 16) LDGA(kb + 3);
        }
    }

#pragma unroll
    for (int mf = 0; mf < 2; mf++) {
#pragma unroll
        for (int nf = 0; nf < 4; nf++) {
            const int cc = wn * 32 + nf * 8 + 2 * t4;
            const int n  = n0 + cc;
            const int cta = (n & 1023) >> 3;
            const int loc = ((n >> 10) << 3) + (n & 7);
            const float bz0 = bias_s[cc], bz1 = bias_s[cc + 1];
#pragma unroll
            for (int e = 0; e < 2; e++) {
                const int rr = wm * 32 + mf * 16 + gid + e * 8;
                const int b = rr & 63, tt = t0 + (rr >> 6);
                float2 v;
                v.x = C[mf][nf][2 * e]     + bz0;
                v.y = C[mf][nf][2 * e + 1] + bz1;
                *(float2*)&d_gates[(((size_t)tt * NCTA + cta) * BATCH + b) * CPC + loc] = v;
            }
        }
    }
#undef LDGA
#undef STSA
#undef CPB
}

// ================= K3: persistent LSTM recurrence ================
// 512 threads, 16 warps = M-split 2 x K-split 8. Per-chunk producer gating.
// SMEM: Ws[32][1032] (132KB) | overlay region: hs[2][64][132] / gs[16][32][34] (69.6KB)
#define WS_STR 1032
#define HS_STR 132
#define GS_STR 34
#define HS_OFF (32 * WS_STR)
#define HS_BUF (64 * HS_STR)
#define OVL_FLOATS (16 * 32 * GS_STR)    // 17408 > 2*HS_BUF (16896)
#define K3_SMEM ((HS_OFF + OVL_FLOATS) * 4)   // 201728 bytes

__global__ __launch_bounds__(512, 1) void k_lstm(const float* __restrict__ whh) {
    extern __shared__ float sm[];
    float* Ws = sm;                 // [32][1032]
    float* hs = sm + HS_OFF;        // [2][64][132]
    float* gs = hs;                 // overlay [16][32][34]
    const uint32_t sbH = smem_u32(hs);

    const int tid  = threadIdx.x;
    const int j    = blockIdx.x;
    const int lane = tid & 31, wid = tid >> 5;
    const int gid  = lane >> 2, t4 = lane & 3;
    const int wm   = wid & 1, kq = wid >> 1;   // M-half, K-eighth

    // build Ws[n][perm(k)] = tf32(whh[k][gcol(n)])
    for (int idx = tid; idx < 32 * HID; idx += 512) {
        const int n = idx >> 10, k = idx & 1023;
        const int gcol = ((n >> 3) << 10) + j * HPC + (n & 7);
        Ws[n * WS_STR + (k & ~7) + p8(k & 7)] = tf32r(whh[(size_t)k * G4 + gcol]);
    }
    __syncthreads();

    const int b0 = tid >> 3, h0 = tid & 7;   // one (batch, hid) pair per thread
    const int pfj = tid & 15;                // flag index within a chunk's producer set
    float creg = 0.f;

#define STAGE(BUF, CH, HP) do { \
    _Pragma("unroll") for (int _i = 0; _i < 4; _i++) { \
        const int _idx = tid + _i * 512; \
        const int _r = _idx >> 5, _f = _idx & 31; \
        cp16_sm(sbH + ((BUF) * HS_BUF + _r * HS_STR + _f * 4) * 4, \
                (HP) + (size_t)_r * HID + (CH) * 128 + _f * 4); \
    } \
    asm volatile("cp.async.commit_group;" ::: "memory"); \
} while (0)

// all threads poll one of the 16 producer flags for chunk CH, acquire, then stage
#define GATE_STAGE(BUF, CH, HP) do { \
    const unsigned* _fp = (const unsigned*)d_flags + (CH) * 16 + pfj; \
    unsigned _v; \
    do { asm volatile("ld.acquire.gpu.global.u32 %0, [%1];" : "=r"(_v) : "l"(_fp)); } \
    while (_v < (unsigned)t); \
    STAGE(BUF, CH, HP); \
} while (0)

    for (int t = 0; t < SEQ; t++) {
        // prefetch this step's input-gate preactivations (4 per thread, overlaps polling)
        const float* gx = d_gates + (((size_t)t * NCTA + j) * BATCH + b0) * CPC + h0;
        float pg[4];
#pragma unroll
        for (int g = 0; g < 4; g++) pg[g] = gx[g * 8];

        float Cf[2][4][4] = {};
        if (t > 0) {
            const float* hp = d_hbuf[(t - 1) & 1];

            GATE_STAGE(0, 0, hp);
            GATE_STAGE(1, 1, hp);
#pragma unroll
            for (int c = 0; c < 8; c++) {
                if (c < 7) asm volatile("cp.async.wait_group 1;" ::: "memory");
                else       asm volatile("cp.async.wait_group 0;" ::: "memory");
                __syncthreads();
                {
                    const float* buf = hs + (c & 1) * HS_BUF;
                    const int kb = kq * 16;
#pragma unroll
                    for (int ks = 0; ks < 2; ks++) {
                        const int cb = kb + ks * 8;
                        float2 au[2], av[2];
#pragma unroll
                        for (int mf = 0; mf < 2; mf++) {
                            const int rr = wm * 32 + mf * 16 + gid;
                            au[mf] = *(const float2*)(buf + rr * HS_STR + cb + 2 * t4);
                            av[mf] = *(const float2*)(buf + (rr + 8) * HS_STR + cb + 2 * t4);
                        }
                        uint32_t bu[4][2];
#pragma unroll
                        for (int nf = 0; nf < 4; nf++) {
                            float2 bv = *(const float2*)(Ws + (nf * 8 + gid) * WS_STR + c * 128 + cb + 2 * t4);
                            bu[nf][0] = __float_as_uint(bv.x);
                            bu[nf][1] = __float_as_uint(bv.y);
                        }
#pragma unroll
                        for (int mf = 0; mf < 2; mf++)
#pragma unroll
                            for (int nf = 0; nf < 4; nf++)
                                mma_tf32(Cf[mf][nf],
                                         __float_as_uint(au[mf].x), __float_as_uint(av[mf].x),
                                         __float_as_uint(au[mf].y), __float_as_uint(av[mf].y),
                                         bu[nf][0], bu[nf][1]);
                    }
                }
                __syncthreads();
                if (c + 2 < 8) GATE_STAGE(c & 1, c + 2, hp);
            }

            // stash partial C to gs[(wm*8+kq)][32][34]
            const int gbase = (wm * 8 + kq) * 32 * GS_STR;
#pragma unroll
            for (int mf = 0; mf < 2; mf++) {
                const int rl = mf * 16 + gid;
#pragma unroll
                for (int nf = 0; nf < 4; nf++) {
                    float2 v0, v1;
                    v0.x = Cf[mf][nf][0]; v0.y = Cf[mf][nf][1];
                    v1.x = Cf[mf][nf][2]; v1.y = Cf[mf][nf][3];
                    *(float2*)&gs[gbase + rl * GS_STR + nf * 8 + 2 * t4]       = v0;
                    *(float2*)&gs[gbase + (rl + 8) * GS_STR + nf * 8 + 2 * t4] = v1;
                }
            }
            __syncthreads();
        }

        // fused LSTM cell: 1 (b,hid) pair per thread; reduce 8 K-slice partials
        float a[4];
#pragma unroll
        for (int g = 0; g < 4; g++) a[g] = pg[g];
        if (t > 0) {
            const int wb = (b0 >> 5) * 8;
            const int rb = (b0 & 31) * GS_STR;
#pragma unroll
            for (int q = 0; q < 8; q++) {
                const int base = (wb + q) * 32 * GS_STR + rb;
#pragma unroll
                for (int g = 0; g < 4; g++) a[g] += gs[base + g * 8 + h0];
            }
        }
        {
            const float gi = sigf(a[0]), gf = sigf(a[1]), gg = tanf_(a[2]), go = sigf(a[3]);
            creg = gf * creg + gi * gg;
            d_hbuf[t & 1][(size_t)b0 * HID + j * HPC + p8(h0)] = go * tanf_(creg);
        }
        __syncthreads();
        if (tid == 0) {
            asm volatile("fence.acq_rel.gpu;" ::: "memory");
            asm volatile("st.release.gpu.global.u32 [%0], %1;"
                         :: "l"((unsigned*)&d_flags[j]), "r"((unsigned)(t + 1)) : "memory");
        }
    }
#undef STAGE
#undef GATE_STAGE
}

// ================= K4: logits (un-permute h) ================
__global__ void k_out(const float* __restrict__ ow, const float* __restrict__ ob,
                      float* __restrict__ out) {
    const int tid = threadIdx.x;
    if (tid >= 128) return;
    const int b = tid >> 1, n = tid & 1;
    const float* h = d_hbuf[1] + (size_t)b * HID;   // step 511 wrote buffer 1
    float acc = ob[n];
    for (int c = 0; c < HID; c++) {
        const int phys = (c & ~7) + p8(c & 7);
        acc += h[phys] * ow[c * 2 + n];
    }
    out[b * 2 + n] = acc;
}

// ================= launch ================
extern "C" void kernel_launch(void* const* d_in, const int* in_sizes, int n_in,
                              void* d_out, int out_size) {
    const int*   x    = (const int*)  d_in[0];
    const float* embT = (const float*)d_in[1];
    const float* bw   = (const float*)d_in[2];
    const float* bb   = (const float*)d_in[3];
    const float* wih  = (const float*)d_in[4];
    const float* whh  = (const float*)d_in[5];
    const float* bih  = (const float*)d_in[6];
    const float* bhh  = (const float*)d_in[7];
    const float* ow   = (const float*)d_in[8];
    const float* ob   = (const float*)d_in[9];
    float*       out  = (float*)d_out;

    cudaFuncSetAttribute(k_gates, cudaFuncAttributeMaxDynamicSharedMemorySize, KG_SMEM);
    cudaFuncSetAttribute(k_lstm,  cudaFuncAttributeMaxDynamicSharedMemorySize, K3_SMEM);

    k_fold<<<dim3(G4 / 64, EMB / 64), 256>>>(bw, wih);
    k_bias<<<dim3(G4 / 256), 256>>>(bb, wih, bih, bhh);
    k_gates<<<dim3(G4 / 64, SEQ / 2), 256, KG_SMEM>>>(x, embT);
    k_lstm<<<NCTA, 512, K3_SMEM>>>(whh);
    k_out<<<1, 128>>>(ow, ob, out);
}